// round 8
// baseline (speedup 1.0000x reference)
#include <cuda_runtime.h>
#include <cuda_bf16.h>
#include <float.h>
#include <cstdint>

// Problem constants (fixed by the dataset)
#define MAX_NODES 100000
#define MAX_TOTAL 1703936   // E + n upper bound (1.6M + 100K, padded)
#define D_FEAT 32
#define D_HID 64
#define D_OUT 64

// Scratch: per-node precomputed terms.
// U[j] = x_j @ W1[:32] + pos_j @ W1[32:35] + b1   (N x 64)
// P[i] = pos_i @ W1[32:35]                        (N x 64)
// Per-edge preactivation = U[src] - P[dst].
__device__ float g_U[MAX_NODES * D_HID];
__device__ float g_P[MAX_NODES * D_HID];
__device__ int g_is64;
// Normalized edge list (int32, self-loops appended): size total = E + n.
__device__ int g_SRC[MAX_TOTAL];
__device__ int g_DST[MAX_TOTAL];

// ---------------------------------------------------------------------------
// PTX helpers
// ---------------------------------------------------------------------------
__device__ __forceinline__ uint32_t smem_to_u32(const void* p) {
    uint32_t a;
    asm("{ .reg .u64 t; cvta.to.shared.u64 t, %1; cvt.u32.u64 %0, t; }"
        : "=r"(a) : "l"(p));
    return a;
}
__device__ __forceinline__ void cp_async16(uint32_t sdst, const void* gsrc) {
    asm volatile("cp.async.cg.shared.global [%0], [%1], 16;"
                 :: "r"(sdst), "l"(gsrc) : "memory");
}
__device__ __forceinline__ void cp_commit() {
    asm volatile("cp.async.commit_group;" ::: "memory");
}
template <int N>
__device__ __forceinline__ void cp_wait() {
    asm volatile("cp.async.wait_group %0;" :: "n"(N) : "memory");
}
__device__ __forceinline__ void bar_pair(int id) {
    asm volatile("bar.sync %0, 64;" :: "r"(id) : "memory");
}
__device__ __forceinline__ void mma_bf16(float* c, const uint32_t* a,
                                         uint32_t b0, uint32_t b1) {
    asm volatile(
        "mma.sync.aligned.m16n8k16.row.col.f32.bf16.bf16.f32 "
        "{%0,%1,%2,%3}, {%4,%5,%6,%7}, {%8,%9}, {%0,%1,%2,%3};"
        : "+f"(c[0]), "+f"(c[1]), "+f"(c[2]), "+f"(c[3])
        : "r"(a[0]), "r"(a[1]), "r"(a[2]), "r"(a[3]), "r"(b0), "r"(b1));
}
__device__ __forceinline__ uint32_t pack_hi(float a, float b) {
    return __byte_perm(__float_as_uint(a), __float_as_uint(b), 0x7632);
}
__device__ __forceinline__ float resid(float x) {
    return x - __uint_as_float(__float_as_uint(x) & 0xFFFF0000u);
}
__device__ __forceinline__ uint32_t pack_lo_rn(float a, float b) {
    __nv_bfloat162 t = __floats2bfloat162_rn(a, b);
    return *(uint32_t*)&t;
}

// ---------------------------------------------------------------------------
// Kernel 0: detect edge_index element width (int64 vs int32).
// ---------------------------------------------------------------------------
__global__ void detect_kernel(const long long* __restrict__ ei64, int E, int n) {
    __shared__ int bad;
    if (threadIdx.x == 0) bad = 0;
    __syncthreads();
    int samples = min(4096, E);
    for (int i = threadIdx.x; i < samples; i += blockDim.x) {
        long long v = ei64[i];
        if (v < 0 || v >= (long long)n) atomicOr(&bad, 1);
    }
    __syncthreads();
    if (threadIdx.x == 0) g_is64 = bad ? 0 : 1;
}

// ---------------------------------------------------------------------------
// Kernel 0b: normalize edge list to int32 with self-loops appended.
// ---------------------------------------------------------------------------
__global__ void convert_edges_kernel(const void* __restrict__ ei_raw,
                                     int E, int n) {
    const int is64 = g_is64;
    const long long* ei64 = (const long long*)ei_raw;
    const int*       ei32 = (const int*)ei_raw;
    const int total = E + n;
    for (int i = blockIdx.x * blockDim.x + threadIdx.x; i < total;
         i += gridDim.x * blockDim.x) {
        int s, d;
        if (i < E) {
            if (is64) { s = (int)ei64[i]; d = (int)ei64[E + i]; }
            else      { s = ei32[i];      d = ei32[E + i]; }
        } else { s = i - E; d = s; }
        g_SRC[i] = s;
        g_DST[i] = d;
    }
}

// ---------------------------------------------------------------------------
// Kernel 1: per-node precompute of U and P (grid-stride).
// ---------------------------------------------------------------------------
__global__ void precompute_kernel(const float* __restrict__ x,
                                  const float* __restrict__ pos,
                                  const float* __restrict__ W1,
                                  const float* __restrict__ b1,
                                  int n) {
    __shared__ float W1s[35 * 64];
    __shared__ float b1s[64];
    for (int i = threadIdx.x; i < 35 * 64; i += blockDim.x) W1s[i] = W1[i];
    if (threadIdx.x < 64) b1s[threadIdx.x] = b1[threadIdx.x];
    __syncthreads();

    const int totalW = n * 64;
    for (int gid = blockIdx.x * blockDim.x + threadIdx.x; gid < totalW;
         gid += gridDim.x * blockDim.x) {
        int node = gid >> 6;
        int k = gid & 63;

        const float* xr = x + node * D_FEAT;
        float acc = b1s[k];
#pragma unroll
        for (int f = 0; f < D_FEAT; f++) acc = fmaf(xr[f], W1s[f * 64 + k], acc);
        float px = pos[node * 3 + 0];
        float py = pos[node * 3 + 1];
        float pz = pos[node * 3 + 2];
        float pp = px * W1s[32 * 64 + k];
        pp = fmaf(py, W1s[33 * 64 + k], pp);
        pp = fmaf(pz, W1s[34 * 64 + k], pp);

        g_U[node * 64 + k] = acc + pp;
        g_P[node * 64 + k] = pp;
    }
}

// ---------------------------------------------------------------------------
// Kernel 2: init output to -FLT_MAX (grid-stride).
// ---------------------------------------------------------------------------
__global__ void init_out_kernel(float* __restrict__ out, int total) {
    for (int i = blockIdx.x * blockDim.x + threadIdx.x; i < total;
         i += gridDim.x * blockDim.x)
        out[i] = -FLT_MAX;
}

__device__ __forceinline__ void atomicMaxF(float* addr, float v) {
    if (v >= 0.0f) atomicMax((int*)addr, __float_as_int(v));
    else           atomicMin((unsigned int*)addr, __float_as_uint(v));
}

// ---------------------------------------------------------------------------
// Kernel 3: persistent HMMA edge kernel with cp.async double buffering.
//
// 256 threads = 8 warps = 4 warp PAIRS. Each pair owns a stream of 16-edge
// groups; within a pair, warp `half` computes output cols [half*32, +32).
// Per group: U rows (16x64 f32) + P rows staged to smem via cp.async (rows
// padded to 72 floats -> conflict-free LDS.64 in compute), 2-stage double
// buffer per pair. B = W2 bf16 hi/lo fragments live in registers (built once).
// D = Ahi@Bhi + Alo@Bhi + Ahi@Blo (rel_err ~1e-5).
// ---------------------------------------------------------------------------
#define ROW_F 72                       // floats per staged row (64 + 8 pad)
#define STAGE_F (32 * ROW_F)           // U rows 0..15, P rows 16..31
#define PAIR_F (2 * STAGE_F)
#define SMEM_F (4 * PAIR_F)            // 4 pairs
#define SMEM_BYTES (SMEM_F * 4)        // 73728

__global__ void __launch_bounds__(256, 2) edge_kernel(
    const float* __restrict__ W2,       // [64 k][64 n] row-major
    const float* __restrict__ b2,       // [64]
    float* __restrict__ out,            // [n, 64]
    int n, int E) {
    extern __shared__ __align__(16) float smemf[];
    const uint32_t sb = smem_to_u32(smemf);

    const int lane = threadIdx.x & 31;
    const int pairLocal = threadIdx.x >> 6;            // 0..3
    const int half = (threadIdx.x >> 5) & 1;           // col half
    const int t64 = threadIdx.x & 63;                  // thread in pair
    const int n0 = half * 32;
    const int barId = 1 + pairLocal;

    const int pairId = (blockIdx.x * blockDim.x + threadIdx.x) >> 6;
    const int nPairs = (gridDim.x * blockDim.x) >> 6;

    const int tg = lane >> 2;   // fragment row group 0..7
    const int tk = lane & 3;    // thread in group

    // ---- Persistent B fragments (W2 bf16 hi/lo) + bias ----
    uint32_t Bhi[4][4][2], Blo[4][4][2];
    float2 bias[4];
#pragma unroll
    for (int nt = 0; nt < 4; nt++) {
        const int colB = n0 + nt * 8 + tg;
        const int colC = n0 + nt * 8 + tk * 2;
        bias[nt] = *(const float2*)&b2[colC];
#pragma unroll
        for (int ks = 0; ks < 4; ks++) {
#pragma unroll
            for (int b = 0; b < 2; b++) {
                int k = ks * 16 + tk * 2 + b * 8;
                float w0 = W2[k * 64 + colB];
                float w1 = W2[(k + 1) * 64 + colB];
                Bhi[nt][ks][b] = pack_hi(w0, w1);
                Blo[nt][ks][b] = pack_lo_rn(resid(w0), resid(w1));
            }
        }
    }

    const int total = E + n;
    const int G = (total + 15) >> 4;

    // Loader role for this thread: row (0..31; 0-15=U, 16-31=P), 128B half hb.
    const int ldRow = t64 >> 1;
    const int ldHb = t64 & 1;
    const uint32_t ldDst =
        sb + (uint32_t)((pairLocal * PAIR_F) + ldRow * ROW_F + ldHb * 32) * 4;

    // Resolve gmem source pointer for a group (issues the index LDG).
    auto prep = [&](int g) -> const float* {
        if (g >= G) return g_U;                    // dummy (pipeline filler)
        int e = g * 16 + (ldRow & 15);
        if (e >= total) return g_U;                // tail dummy row
        int node = (ldRow < 16) ? g_SRC[e] : g_DST[e];
        return ((ldRow < 16) ? g_U : g_P) + node * 64 + ldHb * 32;
    };
    auto issue = [&](const float* gsrc, int s) {
        uint32_t d = ldDst + (uint32_t)(s * STAGE_F) * 4;
#pragma unroll
        for (int i = 0; i < 8; i++) cp_async16(d + i * 16, gsrc + i * 4);
        cp_commit();
    };

    // ---- Pipeline preamble: fill both stages ----
    const float* pNext;
    {
        const float* p0 = prep(pairId);
        issue(p0, 0);
        pNext = prep(pairId + nPairs);
        issue(pNext, 1);
    }

    int s = 0;
    for (int g = pairId, k = 0; g < G; g += nPairs, k++, s ^= 1) {
        cp_wait<1>();          // oldest in-flight group (stage s) complete
        bar_pair(barId);       // partner's half also complete

        // Prefetch: indices for group k+2, epilogue dsts for this group.
        pNext = prep(g + 2 * nPairs);
        const int e0 = g * 16;
        const int eA = e0 + tg;
        const int eB = eA + 8;
        const int dA = (eA < total) ? g_DST[eA] : -1;
        const int dB = (eB < total) ? g_DST[eB] : -1;

        // ---- Compute from stage s ----
        const float* Us = smemf + pairLocal * PAIR_F + s * STAGE_F;
        const float* Ps = Us + 16 * ROW_F;

        float acc[4][4];
#pragma unroll
        for (int nt = 0; nt < 4; nt++)
#pragma unroll
            for (int q = 0; q < 4; q++) acc[nt][q] = 0.0f;

#pragma unroll
        for (int ks = 0; ks < 4; ks++) {
            const int k2 = ks * 16 + tk * 2;
            float2 uA0 = *(const float2*)&Us[tg * ROW_F + k2];
            float2 pA0 = *(const float2*)&Ps[tg * ROW_F + k2];
            float2 uB0 = *(const float2*)&Us[(tg + 8) * ROW_F + k2];
            float2 pB0 = *(const float2*)&Ps[(tg + 8) * ROW_F + k2];
            float2 uA8 = *(const float2*)&Us[tg * ROW_F + k2 + 8];
            float2 pA8 = *(const float2*)&Ps[tg * ROW_F + k2 + 8];
            float2 uB8 = *(const float2*)&Us[(tg + 8) * ROW_F + k2 + 8];
            float2 pB8 = *(const float2*)&Ps[(tg + 8) * ROW_F + k2 + 8];

            float hA0x = fmaxf(uA0.x - pA0.x, 0.0f), hA0y = fmaxf(uA0.y - pA0.y, 0.0f);
            float hB0x = fmaxf(uB0.x - pB0.x, 0.0f), hB0y = fmaxf(uB0.y - pB0.y, 0.0f);
            float hA8x = fmaxf(uA8.x - pA8.x, 0.0f), hA8y = fmaxf(uA8.y - pA8.y, 0.0f);
            float hB8x = fmaxf(uB8.x - pB8.x, 0.0f), hB8y = fmaxf(uB8.y - pB8.y, 0.0f);

            uint32_t Ahi[4], Alo[4];
            Ahi[0] = pack_hi(hA0x, hA0y);
            Ahi[1] = pack_hi(hB0x, hB0y);
            Ahi[2] = pack_hi(hA8x, hA8y);
            Ahi[3] = pack_hi(hB8x, hB8y);
            Alo[0] = pack_lo_rn(resid(hA0x), resid(hA0y));
            Alo[1] = pack_lo_rn(resid(hB0x), resid(hB0y));
            Alo[2] = pack_lo_rn(resid(hA8x), resid(hA8y));
            Alo[3] = pack_lo_rn(resid(hB8x), resid(hB8y));

#pragma unroll
            for (int nt = 0; nt < 4; nt++) {
                mma_bf16(acc[nt], Ahi, Bhi[nt][ks][0], Bhi[nt][ks][1]);
                mma_bf16(acc[nt], Alo, Bhi[nt][ks][0], Bhi[nt][ks][1]);
                mma_bf16(acc[nt], Ahi, Blo[nt][ks][0], Blo[nt][ks][1]);
            }
        }

        // ---- Epilogue: bias + pre-checked scatter-max ----
        if (dA >= 0) {
            float* o = out + dA * 64 + n0 + tk * 2;
#pragma unroll
            for (int nt = 0; nt < 4; nt++) {
                float v0 = acc[nt][0] + bias[nt].x;
                float v1 = acc[nt][1] + bias[nt].y;
                float2 cur = *(const float2*)(o + nt * 8);
                if (v0 > cur.x) atomicMaxF(o + nt * 8, v0);
                if (v1 > cur.y) atomicMaxF(o + nt * 8 + 1, v1);
            }
        }
        if (dB >= 0) {
            float* o = out + dB * 64 + n0 + tk * 2;
#pragma unroll
            for (int nt = 0; nt < 4; nt++) {
                float v2 = acc[nt][2] + bias[nt].x;
                float v3 = acc[nt][3] + bias[nt].y;
                float2 cur = *(const float2*)(o + nt * 8);
                if (v2 > cur.x) atomicMaxF(o + nt * 8, v2);
                if (v3 > cur.y) atomicMaxF(o + nt * 8 + 1, v3);
            }
        }

        bar_pair(barId);       // partner done reading stage s
        issue(pNext, s);       // refill stage s with group k+2
    }
    cp_wait<0>();              // drain before exit
}

// ---------------------------------------------------------------------------
// Launch
// ---------------------------------------------------------------------------
extern "C" void kernel_launch(void* const* d_in, const int* in_sizes, int n_in,
                              void* d_out, int out_size) {
    const float* x   = (const float*)d_in[0];    // [n, 32]
    const float* pos = (const float*)d_in[1];    // [n, 3]
    const void*  ei  = d_in[2];                  // [2, E] int64 or int32
    const float* W1  = (const float*)d_in[3];    // [35, 64]
    const float* b1  = (const float*)d_in[4];    // [64]
    const float* W2  = (const float*)d_in[5];    // [64, 64]
    const float* b2  = (const float*)d_in[6];    // [64]
    float*       out = (float*)d_out;            // [n, 64]

    int n = in_sizes[0] / D_FEAT;
    int E = in_sizes[2] / 2;

    cudaFuncSetAttribute(edge_kernel, cudaFuncAttributeMaxDynamicSharedMemorySize,
                         SMEM_BYTES);

    // 0) detect edge_index dtype, then normalize to int32 with self-loops
    detect_kernel<<<1, 256>>>((const long long*)ei, E, n);
    convert_edges_kernel<<<1480, 256>>>(ei, E, n);
    // 1) per-node precompute (grid-stride)
    precompute_kernel<<<1480, 256>>>(x, pos, W1, b1, n);
    // 2) init output (grid-stride)
    init_out_kernel<<<1480, 256>>>(out, n * 64);
    // 3) persistent double-buffered HMMA edge kernel (2 CTAs/SM)
    edge_kernel<<<296, 256, SMEM_BYTES>>>(W2, b2, out, n, E);
}

// round 9
// speedup vs baseline: 1.9673x; 1.9673x over previous
#include <cuda_runtime.h>
#include <cuda_bf16.h>
#include <float.h>
#include <cstdint>

// Problem constants (fixed by the dataset)
#define MAX_NODES 100000
#define MAX_TOTAL 1703936   // E + n upper bound
#define D_FEAT 32
#define D_HID 64
#define D_OUT 64
#define TILE_E 64
#define H_STRIDE 68   // floats per H row (64 + pad, 16B-aligned)

// Scratch: per-node precomputed terms.
// U[j] = x_j @ W1[:32] + pos_j @ W1[32:35] + b1   (N x 64)
// P[i] = pos_i @ W1[32:35]                        (N x 64)
// Per-edge preactivation = U[src] - P[dst].
__device__ float g_U[MAX_NODES * D_HID];
__device__ float g_P[MAX_NODES * D_HID];
__device__ int g_is64;
// Normalized edge list (int32, self-loops appended): size total = E + n.
__device__ int g_SRC[MAX_TOTAL];
__device__ int g_DST[MAX_TOTAL];

// ---------------------------------------------------------------------------
// packed fp32x2 helpers (bit-exact pair of fp32 FMAs)
// ---------------------------------------------------------------------------
__device__ __forceinline__ void ffma2(unsigned long long& d,
                                      unsigned long long a,
                                      unsigned long long b) {
    asm("fma.rn.f32x2 %0, %1, %2, %0;" : "+l"(d) : "l"(a), "l"(b));
}
__device__ __forceinline__ unsigned long long packdup(float x) {
    unsigned long long r;
    asm("mov.b64 %0, {%1, %1};" : "=l"(r) : "f"(x));
    return r;
}
__device__ __forceinline__ void unpack2(unsigned long long v, float& lo, float& hi) {
    asm("mov.b64 {%0, %1}, %2;" : "=f"(lo), "=f"(hi) : "l"(v));
}

// ---------------------------------------------------------------------------
// Kernel 0: detect edge_index element width (int64 vs int32).
// ---------------------------------------------------------------------------
__global__ void detect_kernel(const long long* __restrict__ ei64, int E, int n) {
    __shared__ int bad;
    if (threadIdx.x == 0) bad = 0;
    __syncthreads();
    int samples = min(4096, E);
    for (int i = threadIdx.x; i < samples; i += blockDim.x) {
        long long v = ei64[i];
        if (v < 0 || v >= (long long)n) atomicOr(&bad, 1);
    }
    __syncthreads();
    if (threadIdx.x == 0) g_is64 = bad ? 0 : 1;
}

// ---------------------------------------------------------------------------
// Kernel 0b: normalize edge list to int32 with self-loops appended.
// ---------------------------------------------------------------------------
__global__ void convert_edges_kernel(const void* __restrict__ ei_raw,
                                     int E, int n) {
    const int is64 = g_is64;
    const long long* ei64 = (const long long*)ei_raw;
    const int*       ei32 = (const int*)ei_raw;
    const int total = E + n;
    for (int i = blockIdx.x * blockDim.x + threadIdx.x; i < total;
         i += gridDim.x * blockDim.x) {
        int s, d;
        if (i < E) {
            if (is64) { s = (int)ei64[i]; d = (int)ei64[E + i]; }
            else      { s = ei32[i];      d = ei32[E + i]; }
        } else { s = i - E; d = s; }
        g_SRC[i] = s;
        g_DST[i] = d;
    }
}

// ---------------------------------------------------------------------------
// Kernel 1: per-node precompute of U and P (grid-stride).
// ---------------------------------------------------------------------------
__global__ void precompute_kernel(const float* __restrict__ x,
                                  const float* __restrict__ pos,
                                  const float* __restrict__ W1,
                                  const float* __restrict__ b1,
                                  int n) {
    __shared__ float W1s[35 * 64];
    __shared__ float b1s[64];
    for (int i = threadIdx.x; i < 35 * 64; i += blockDim.x) W1s[i] = W1[i];
    if (threadIdx.x < 64) b1s[threadIdx.x] = b1[threadIdx.x];
    __syncthreads();

    const int totalW = n * 64;
    for (int gid = blockIdx.x * blockDim.x + threadIdx.x; gid < totalW;
         gid += gridDim.x * blockDim.x) {
        int node = gid >> 6;
        int k = gid & 63;

        const float* xr = x + node * D_FEAT;
        float acc = b1s[k];
#pragma unroll
        for (int f = 0; f < D_FEAT; f++) acc = fmaf(xr[f], W1s[f * 64 + k], acc);
        float px = pos[node * 3 + 0];
        float py = pos[node * 3 + 1];
        float pz = pos[node * 3 + 2];
        float pp = px * W1s[32 * 64 + k];
        pp = fmaf(py, W1s[33 * 64 + k], pp);
        pp = fmaf(pz, W1s[34 * 64 + k], pp);

        g_U[node * 64 + k] = acc + pp;
        g_P[node * 64 + k] = pp;
    }
}

// ---------------------------------------------------------------------------
// Kernel 2: init output to -FLT_MAX (grid-stride).
// ---------------------------------------------------------------------------
__global__ void init_out_kernel(float* __restrict__ out, int total) {
    for (int i = blockIdx.x * blockDim.x + threadIdx.x; i < total;
         i += gridDim.x * blockDim.x)
        out[i] = -FLT_MAX;
}

__device__ __forceinline__ void atomicMaxF(float* addr, float v) {
    if (v >= 0.0f) atomicMax((int*)addr, __float_as_int(v));
    else           atomicMin((unsigned int*)addr, __float_as_uint(v));
}

// ---------------------------------------------------------------------------
// Kernel 3: persistent scalar-FFMA2 edge kernel.
// 128 threads/CTA, 6 CTAs/SM, tile = 64 edges x 64 outputs.
// Thread tile = 4 edges x 8 outputs:
//   cg = tid & 7   -> cols {cg*4..cg*4+3} and {32+cg*4..32+cg*4+3}
//   e0 = tid >> 3  -> edges e0, e0+16, e0+32, e0+48
// Per-warp: 4 distinct H rows (broadcast, 1 phase); w chunks cover banks
// 0..31 exactly (1 phase). W2 staged in smem ONCE per persistent CTA.
// ---------------------------------------------------------------------------
__global__ void __launch_bounds__(128, 6) edge_kernel(
    const float* __restrict__ W2,       // [64 k][64 n] row-major
    const float* __restrict__ b2,       // [64]
    float* __restrict__ out,            // [n, 64]
    int n, int E) {
    extern __shared__ float smem[];
    float* Hs  = smem;                       // TILE_E * H_STRIDE
    float* W2s = smem + TILE_E * H_STRIDE;   // 64 * 64
    float* b2s = W2s + 64 * 64;              // 64
    int*   dsts = (int*)(b2s + 64);          // TILE_E

    const int tid = threadIdx.x;
    // ---- Stage W2 + b2 once per persistent CTA ----
    for (int i = tid; i < 64 * 64; i += 128) W2s[i] = W2[i];
    if (tid < 64) b2s[tid] = b2[tid];
    __syncthreads();

    const int total = E + n;
    const int nTiles = (total + TILE_E - 1) / TILE_E;

    const int c  = tid & 15;   // float4 chunk of 64-wide row
    const int es = tid >> 4;   // 8 rows per pass
    const int cg = tid & 7;
    const int e0 = tid >> 3;        // 0..15
    const int kb1 = cg * 4;
    const int kb2 = 32 + cg * 4;
    const float4 bbA = *(const float4*)&b2s[kb1];
    const float4 bbB = *(const float4*)&b2s[kb2];

    for (int tile = blockIdx.x; tile < nTiles; tile += gridDim.x) {
        const int base = tile * TILE_E;

        // ---------------- Stage 1: gather + relu into Hs ----------------
#pragma unroll
        for (int j = 0; j < TILE_E / 8; j++) {
            int el = j * 8 + es;
            int eg = base + el;
            float4 h = make_float4(0.f, 0.f, 0.f, 0.f);
            int d = -1;
            if (eg < total) {
                int s = g_SRC[eg];
                d = g_DST[eg];
                float4 u = *(const float4*)&g_U[s * 64 + c * 4];
                float4 p = *(const float4*)&g_P[d * 64 + c * 4];
                h.x = fmaxf(u.x - p.x, 0.0f);
                h.y = fmaxf(u.y - p.y, 0.0f);
                h.z = fmaxf(u.z - p.z, 0.0f);
                h.w = fmaxf(u.w - p.w, 0.0f);
            }
            if (c == 0) dsts[el] = d;
            *(float4*)&Hs[el * H_STRIDE + c * 4] = h;
        }
        __syncthreads();

        // ---------------- Stage 2: GEMM (4 edges x 8 cols / thread) -------
        unsigned long long acc[4][4];
#pragma unroll
        for (int i = 0; i < 4; i++)
#pragma unroll
            for (int jq = 0; jq < 4; jq++) acc[i][jq] = 0ull;

#pragma unroll
        for (int m4 = 0; m4 < 16; m4++) {
            float h0[4], h1[4], h2[4], h3[4];
            {
                float4 t;
                t = *(const float4*)&Hs[(e0 +  0) * H_STRIDE + m4 * 4];
                h0[0] = t.x; h0[1] = t.y; h0[2] = t.z; h0[3] = t.w;
                t = *(const float4*)&Hs[(e0 + 16) * H_STRIDE + m4 * 4];
                h1[0] = t.x; h1[1] = t.y; h1[2] = t.z; h1[3] = t.w;
                t = *(const float4*)&Hs[(e0 + 32) * H_STRIDE + m4 * 4];
                h2[0] = t.x; h2[1] = t.y; h2[2] = t.z; h2[3] = t.w;
                t = *(const float4*)&Hs[(e0 + 48) * H_STRIDE + m4 * 4];
                h3[0] = t.x; h3[1] = t.y; h3[2] = t.z; h3[3] = t.w;
            }
#pragma unroll
            for (int mm = 0; mm < 4; mm++) {
                const int m = m4 * 4 + mm;
                ulonglong2 wA = *(const ulonglong2*)&W2s[m * 64 + kb1];
                ulonglong2 wB = *(const ulonglong2*)&W2s[m * 64 + kb2];
                unsigned long long hb;
                hb = packdup(h0[mm]);
                ffma2(acc[0][0], hb, wA.x); ffma2(acc[0][1], hb, wA.y);
                ffma2(acc[0][2], hb, wB.x); ffma2(acc[0][3], hb, wB.y);
                hb = packdup(h1[mm]);
                ffma2(acc[1][0], hb, wA.x); ffma2(acc[1][1], hb, wA.y);
                ffma2(acc[1][2], hb, wB.x); ffma2(acc[1][3], hb, wB.y);
                hb = packdup(h2[mm]);
                ffma2(acc[2][0], hb, wA.x); ffma2(acc[2][1], hb, wA.y);
                ffma2(acc[2][2], hb, wB.x); ffma2(acc[2][3], hb, wB.y);
                hb = packdup(h3[mm]);
                ffma2(acc[3][0], hb, wA.x); ffma2(acc[3][1], hb, wA.y);
                ffma2(acc[3][2], hb, wB.x); ffma2(acc[3][3], hb, wB.y);
            }
        }

        // ---------------- Stage 3: scatter-max ----------------
#pragma unroll
        for (int i = 0; i < 4; i++) {
            int d = dsts[e0 + 16 * i];
            if (d < 0) continue;
            float v0, v1, v2, v3, v4, v5, v6, v7;
            unpack2(acc[i][0], v0, v1);
            unpack2(acc[i][1], v2, v3);
            unpack2(acc[i][2], v4, v5);
            unpack2(acc[i][3], v6, v7);
            v0 += bbA.x; v1 += bbA.y; v2 += bbA.z; v3 += bbA.w;
            v4 += bbB.x; v5 += bbB.y; v6 += bbB.z; v7 += bbB.w;
            float* oA = out + (long long)d * 64 + kb1;
            float* oB = out + (long long)d * 64 + kb2;
            float4 curA = *(const float4*)oA;
            float4 curB = *(const float4*)oB;
            if (v0 > curA.x) atomicMaxF(oA + 0, v0);
            if (v1 > curA.y) atomicMaxF(oA + 1, v1);
            if (v2 > curA.z) atomicMaxF(oA + 2, v2);
            if (v3 > curA.w) atomicMaxF(oA + 3, v3);
            if (v4 > curB.x) atomicMaxF(oB + 0, v4);
            if (v5 > curB.y) atomicMaxF(oB + 1, v5);
            if (v6 > curB.z) atomicMaxF(oB + 2, v6);
            if (v7 > curB.w) atomicMaxF(oB + 3, v7);
        }
        __syncthreads();   // H reuse safe for next tile
    }
}

// ---------------------------------------------------------------------------
// Launch
// ---------------------------------------------------------------------------
extern "C" void kernel_launch(void* const* d_in, const int* in_sizes, int n_in,
                              void* d_out, int out_size) {
    const float* x   = (const float*)d_in[0];    // [n, 32]
    const float* pos = (const float*)d_in[1];    // [n, 3]
    const void*  ei  = d_in[2];                  // [2, E] int64 or int32
    const float* W1  = (const float*)d_in[3];    // [35, 64]
    const float* b1  = (const float*)d_in[4];    // [64]
    const float* W2  = (const float*)d_in[5];    // [64, 64]
    const float* b2  = (const float*)d_in[6];    // [64]
    float*       out = (float*)d_out;            // [n, 64]

    int n = in_sizes[0] / D_FEAT;
    int E = in_sizes[2] / 2;

    const int smemBytes = (TILE_E * H_STRIDE + 64 * 64 + 64) * 4 + TILE_E * 4;
    cudaFuncSetAttribute(edge_kernel, cudaFuncAttributeMaxDynamicSharedMemorySize,
                         smemBytes);

    // 0) detect edge_index dtype, then normalize to int32 with self-loops
    detect_kernel<<<1, 256>>>((const long long*)ei, E, n);
    convert_edges_kernel<<<1480, 256>>>(ei, E, n);
    // 1) per-node precompute (grid-stride)
    precompute_kernel<<<1480, 256>>>(x, pos, W1, b1, n);
    // 2) init output (grid-stride)
    init_out_kernel<<<1480, 256>>>(out, n * 64);
    // 3) persistent edge kernel: 6 CTAs/SM x 148 SMs
    edge_kernel<<<888, 128, smemBytes>>>(W2, b2, out, n, E);
}

// round 10
// speedup vs baseline: 1.9870x; 1.0100x over previous
#include <cuda_runtime.h>
#include <cuda_bf16.h>
#include <float.h>
#include <cstdint>

// Problem constants (fixed by the dataset)
#define MAX_NODES 100000
#define MAX_TOTAL 1703936   // E + n upper bound
#define D_FEAT 32
#define D_HID 64
#define D_OUT 64
#define TILE_E 64
#define H_STRIDE 68   // floats per H row (64 + pad, 16B-aligned)

// Scratch: per-node precomputed terms.
// U[j] = x_j @ W1[:32] + pos_j @ W1[32:35] + b1   (N x 64)
// P[i] = pos_i @ W1[32:35]                        (N x 64)
// Per-edge preactivation = U[src] - P[dst].
__device__ float g_U[MAX_NODES * D_HID];
__device__ float g_P[MAX_NODES * D_HID];
__device__ int g_is64;
// Normalized edge list (int32, self-loops appended): size total = E + n.
__device__ int g_SRC[MAX_TOTAL];
__device__ int g_DST[MAX_TOTAL];

// ---------------------------------------------------------------------------
// packed fp32x2 helpers (bit-exact pair of fp32 FMAs)
// ---------------------------------------------------------------------------
__device__ __forceinline__ void ffma2(unsigned long long& d,
                                      unsigned long long a,
                                      unsigned long long b) {
    asm("fma.rn.f32x2 %0, %1, %2, %0;" : "+l"(d) : "l"(a), "l"(b));
}
__device__ __forceinline__ unsigned long long packdup(float x) {
    unsigned long long r;
    asm("mov.b64 %0, {%1, %1};" : "=l"(r) : "f"(x));
    return r;
}
__device__ __forceinline__ void unpack2(unsigned long long v, float& lo, float& hi) {
    asm("mov.b64 {%0, %1}, %2;" : "=f"(lo), "=f"(hi) : "l"(v));
}
__device__ __forceinline__ void prefetchL2(const void* p) {
    asm volatile("prefetch.global.L2 [%0];" :: "l"(p));
}

// ---------------------------------------------------------------------------
// Kernel 0: detect edge_index element width (int64 vs int32).
// ---------------------------------------------------------------------------
__global__ void detect_kernel(const long long* __restrict__ ei64, int E, int n) {
    __shared__ int bad;
    if (threadIdx.x == 0) bad = 0;
    __syncthreads();
    int samples = min(4096, E);
    for (int i = threadIdx.x; i < samples; i += blockDim.x) {
        long long v = ei64[i];
        if (v < 0 || v >= (long long)n) atomicOr(&bad, 1);
    }
    __syncthreads();
    if (threadIdx.x == 0) g_is64 = bad ? 0 : 1;
}

// ---------------------------------------------------------------------------
// Kernel 0b: normalize edge list to int32 with self-loops appended.
// ---------------------------------------------------------------------------
__global__ void convert_edges_kernel(const void* __restrict__ ei_raw,
                                     int E, int n) {
    const int is64 = g_is64;
    const long long* ei64 = (const long long*)ei_raw;
    const int*       ei32 = (const int*)ei_raw;
    const int total = E + n;
    for (int i = blockIdx.x * blockDim.x + threadIdx.x; i < total;
         i += gridDim.x * blockDim.x) {
        int s, d;
        if (i < E) {
            if (is64) { s = (int)ei64[i]; d = (int)ei64[E + i]; }
            else      { s = ei32[i];      d = ei32[E + i]; }
        } else { s = i - E; d = s; }
        g_SRC[i] = s;
        g_DST[i] = d;
    }
}

// ---------------------------------------------------------------------------
// Kernel 1: per-node precompute of U and P (grid-stride) + out init fused
// (same (node, k) index space; out gets -FLT_MAX).
// ---------------------------------------------------------------------------
__global__ void precompute_kernel(const float* __restrict__ x,
                                  const float* __restrict__ pos,
                                  const float* __restrict__ W1,
                                  const float* __restrict__ b1,
                                  float* __restrict__ out,
                                  int n) {
    __shared__ float W1s[35 * 64];
    __shared__ float b1s[64];
    for (int i = threadIdx.x; i < 35 * 64; i += blockDim.x) W1s[i] = W1[i];
    if (threadIdx.x < 64) b1s[threadIdx.x] = b1[threadIdx.x];
    __syncthreads();

    const int totalW = n * 64;
    for (int gid = blockIdx.x * blockDim.x + threadIdx.x; gid < totalW;
         gid += gridDim.x * blockDim.x) {
        int node = gid >> 6;
        int k = gid & 63;

        const float* xr = x + node * D_FEAT;
        float acc = b1s[k];
#pragma unroll
        for (int f = 0; f < D_FEAT; f++) acc = fmaf(xr[f], W1s[f * 64 + k], acc);
        float px = pos[node * 3 + 0];
        float py = pos[node * 3 + 1];
        float pz = pos[node * 3 + 2];
        float pp = px * W1s[32 * 64 + k];
        pp = fmaf(py, W1s[33 * 64 + k], pp);
        pp = fmaf(pz, W1s[34 * 64 + k], pp);

        g_U[node * 64 + k] = acc + pp;
        g_P[node * 64 + k] = pp;
        out[gid] = -FLT_MAX;
    }
}

__device__ __forceinline__ void atomicMaxF(float* addr, float v) {
    if (v >= 0.0f) atomicMax((int*)addr, __float_as_int(v));
    else           atomicMin((unsigned int*)addr, __float_as_uint(v));
}

// ---------------------------------------------------------------------------
// Kernel 3: persistent scalar-FFMA2 edge kernel.
// 128 threads/CTA, 6 CTAs/SM, tile = 64 edges x 64 outputs.
// Thread tile = 4 edges x 8 outputs:
//   cg = tid & 7   -> cols {cg*4..cg*4+3} and {32+cg*4..32+cg*4+3}
//   e0 = tid >> 3  -> edges e0, e0+16, e0+32, e0+48
// Gather phase also issues L2 prefetches for the epilogue's out[] rows so the
// pre-check loads after the GEMM hit cache instead of stalling on L2.
// ---------------------------------------------------------------------------
__global__ void __launch_bounds__(128, 6) edge_kernel(
    const float* __restrict__ W2,       // [64 k][64 n] row-major
    const float* __restrict__ b2,       // [64]
    float* __restrict__ out,            // [n, 64]
    int n, int E) {
    extern __shared__ float smem[];
    float* Hs  = smem;                       // TILE_E * H_STRIDE
    float* W2s = smem + TILE_E * H_STRIDE;   // 64 * 64
    float* b2s = W2s + 64 * 64;              // 64
    int*   dsts = (int*)(b2s + 64);          // TILE_E

    const int tid = threadIdx.x;
    // ---- Stage W2 + b2 once per persistent CTA ----
    for (int i = tid; i < 64 * 64; i += 128) W2s[i] = W2[i];
    if (tid < 64) b2s[tid] = b2[tid];
    __syncthreads();

    const int total = E + n;
    const int nTiles = (total + TILE_E - 1) / TILE_E;

    const int c  = tid & 15;   // float4 chunk of 64-wide row
    const int es = tid >> 4;   // 8 rows per pass
    const int cg = tid & 7;
    const int e0 = tid >> 3;        // 0..15
    const int kb1 = cg * 4;
    const int kb2 = 32 + cg * 4;
    const float4 bbA = *(const float4*)&b2s[kb1];
    const float4 bbB = *(const float4*)&b2s[kb2];

    for (int tile = blockIdx.x; tile < nTiles; tile += gridDim.x) {
        const int base = tile * TILE_E;

        // ---------------- Stage 1: gather + relu into Hs ----------------
#pragma unroll
        for (int j = 0; j < TILE_E / 8; j++) {
            int el = j * 8 + es;
            int eg = base + el;
            float4 h = make_float4(0.f, 0.f, 0.f, 0.f);
            int d = -1;
            if (eg < total) {
                int s = g_SRC[eg];
                d = g_DST[eg];
                float4 u = *(const float4*)&g_U[s * 64 + c * 4];
                float4 p = *(const float4*)&g_P[d * 64 + c * 4];
                h.x = fmaxf(u.x - p.x, 0.0f);
                h.y = fmaxf(u.y - p.y, 0.0f);
                h.z = fmaxf(u.z - p.z, 0.0f);
                h.w = fmaxf(u.w - p.w, 0.0f);
            }
            if (c == 0) {
                dsts[el] = d;
                if (d >= 0) {
                    // Warm L2/L1 for the epilogue pre-check reads (256B row).
                    prefetchL2(out + (long long)d * 64);
                    prefetchL2(out + (long long)d * 64 + 32);
                }
            }
            *(float4*)&Hs[el * H_STRIDE + c * 4] = h;
        }
        __syncthreads();

        // ---------------- Stage 2: GEMM (4 edges x 8 cols / thread) -------
        unsigned long long acc[4][4];
#pragma unroll
        for (int i = 0; i < 4; i++)
#pragma unroll
            for (int jq = 0; jq < 4; jq++) acc[i][jq] = 0ull;

#pragma unroll
        for (int m4 = 0; m4 < 16; m4++) {
            float h0[4], h1[4], h2[4], h3[4];
            {
                float4 t;
                t = *(const float4*)&Hs[(e0 +  0) * H_STRIDE + m4 * 4];
                h0[0] = t.x; h0[1] = t.y; h0[2] = t.z; h0[3] = t.w;
                t = *(const float4*)&Hs[(e0 + 16) * H_STRIDE + m4 * 4];
                h1[0] = t.x; h1[1] = t.y; h1[2] = t.z; h1[3] = t.w;
                t = *(const float4*)&Hs[(e0 + 32) * H_STRIDE + m4 * 4];
                h2[0] = t.x; h2[1] = t.y; h2[2] = t.z; h2[3] = t.w;
                t = *(const float4*)&Hs[(e0 + 48) * H_STRIDE + m4 * 4];
                h3[0] = t.x; h3[1] = t.y; h3[2] = t.z; h3[3] = t.w;
            }
#pragma unroll
            for (int mm = 0; mm < 4; mm++) {
                const int m = m4 * 4 + mm;
                ulonglong2 wA = *(const ulonglong2*)&W2s[m * 64 + kb1];
                ulonglong2 wB = *(const ulonglong2*)&W2s[m * 64 + kb2];
                unsigned long long hb;
                hb = packdup(h0[mm]);
                ffma2(acc[0][0], hb, wA.x); ffma2(acc[0][1], hb, wA.y);
                ffma2(acc[0][2], hb, wB.x); ffma2(acc[0][3], hb, wB.y);
                hb = packdup(h1[mm]);
                ffma2(acc[1][0], hb, wA.x); ffma2(acc[1][1], hb, wA.y);
                ffma2(acc[1][2], hb, wB.x); ffma2(acc[1][3], hb, wB.y);
                hb = packdup(h2[mm]);
                ffma2(acc[2][0], hb, wA.x); ffma2(acc[2][1], hb, wA.y);
                ffma2(acc[2][2], hb, wB.x); ffma2(acc[2][3], hb, wB.y);
                hb = packdup(h3[mm]);
                ffma2(acc[3][0], hb, wA.x); ffma2(acc[3][1], hb, wA.y);
                ffma2(acc[3][2], hb, wB.x); ffma2(acc[3][3], hb, wB.y);
            }
        }

        // ---------------- Stage 3: scatter-max ----------------
#pragma unroll
        for (int i = 0; i < 4; i++) {
            int d = dsts[e0 + 16 * i];
            if (d < 0) continue;
            float v0, v1, v2, v3, v4, v5, v6, v7;
            unpack2(acc[i][0], v0, v1);
            unpack2(acc[i][1], v2, v3);
            unpack2(acc[i][2], v4, v5);
            unpack2(acc[i][3], v6, v7);
            v0 += bbA.x; v1 += bbA.y; v2 += bbA.z; v3 += bbA.w;
            v4 += bbB.x; v5 += bbB.y; v6 += bbB.z; v7 += bbB.w;
            float* oA = out + (long long)d * 64 + kb1;
            float* oB = out + (long long)d * 64 + kb2;
            float4 curA = *(const float4*)oA;
            float4 curB = *(const float4*)oB;
            if (v0 > curA.x) atomicMaxF(oA + 0, v0);
            if (v1 > curA.y) atomicMaxF(oA + 1, v1);
            if (v2 > curA.z) atomicMaxF(oA + 2, v2);
            if (v3 > curA.w) atomicMaxF(oA + 3, v3);
            if (v4 > curB.x) atomicMaxF(oB + 0, v4);
            if (v5 > curB.y) atomicMaxF(oB + 1, v5);
            if (v6 > curB.z) atomicMaxF(oB + 2, v6);
            if (v7 > curB.w) atomicMaxF(oB + 3, v7);
        }
        __syncthreads();   // H reuse safe for next tile
    }
}

// ---------------------------------------------------------------------------
// Launch
// ---------------------------------------------------------------------------
extern "C" void kernel_launch(void* const* d_in, const int* in_sizes, int n_in,
                              void* d_out, int out_size) {
    const float* x   = (const float*)d_in[0];    // [n, 32]
    const float* pos = (const float*)d_in[1];    // [n, 3]
    const void*  ei  = d_in[2];                  // [2, E] int64 or int32
    const float* W1  = (const float*)d_in[3];    // [35, 64]
    const float* b1  = (const float*)d_in[4];    // [64]
    const float* W2  = (const float*)d_in[5];    // [64, 64]
    const float* b2  = (const float*)d_in[6];    // [64]
    float*       out = (float*)d_out;            // [n, 64]

    int n = in_sizes[0] / D_FEAT;
    int E = in_sizes[2] / 2;

    const int smemBytes = (TILE_E * H_STRIDE + 64 * 64 + 64) * 4 + TILE_E * 4;
    cudaFuncSetAttribute(edge_kernel, cudaFuncAttributeMaxDynamicSharedMemorySize,
                         smemBytes);

    // 0) detect edge_index dtype, then normalize to int32 with self-loops
    detect_kernel<<<1, 256>>>((const long long*)ei, E, n);
    convert_edges_kernel<<<1480, 256>>>(ei, E, n);
    // 1) per-node precompute + out init (fused, grid-stride)
    precompute_kernel<<<1480, 256>>>(x, pos, W1, b1, out, n);
    // 2) persistent edge kernel: 6 CTAs/SM x 148 SMs
    edge_kernel<<<888, 128, smemBytes>>>(W2, b2, out, n, E);
}